// round 15
// baseline (speedup 1.0000x reference)
#include <cuda_runtime.h>
#include <cuda_bf16.h>
#include <cstdint>

// RoIAlign: feat [4,256,100,100] f32, rois [512,5] f32 -> out [512,256,7,7] f32
// SPATIAL_SCALE=0.25, SAMPLING_RATIO=2, ALIGNED=true, OUT 7x7.
//
// Warp-pair pipelines, QUAD-buffered cp.async, TWO channels per compute
// iteration (dual accumulators, 32 independent LDS -> 2x MLP), one barrier
// pair per 2 channels. Taps as absolute smem addresses (buffer 0); buffers
// 1-3 via +2800/+5600/+8400 ld.shared immediates. 4 pairs/block, 32
// channels/block, grid (512,8), (256,4).

#define FH 100
#define FW 100
#define FC 256
#define OUTHW 49
#define RROWS 25          // max region rows
#define RSTRIDE 28        // region row stride in floats (mult of 4)
#define PAIRS 4           // warp pairs per block
#define CSPLIT 8          // channel-split blocks per RoI
#define CPB (FC / CSPLIT) // 32 channels per block
#define CPP (CPB / PAIRS) // 8 channels per pair
#define BUFB (RROWS * RSTRIDE * 4)  // 2800 bytes per buffer

#define CP_COMMIT asm volatile("cp.async.commit_group;\n" ::)
#define CP_WAIT(n) asm volatile("cp.async.wait_group %0;\n" :: "n"(n))
#define BAR64(id) asm volatile("bar.sync %0, 64;\n" :: "r"(id) : "memory")

__device__ __forceinline__ void cp16(uint32_t saddr, const float* g) {
    asm volatile("cp.async.cg.shared.global [%0], [%1], 16;\n" :: "r"(saddr), "l"(g));
}
template<int OFF>
__device__ __forceinline__ float ldsI(uint32_t a) {
    float v; asm volatile("ld.shared.f32 %0, [%1+%2];" : "=f"(v) : "r"(a), "n"(OFF));
    return v;
}

// compute two channels (buffers at immediates OA, OB) with dual accumulators
template<int OA, int OB>
__device__ __forceinline__ void compute2(const uint32_t* a16,
                                         const float* wy, const float* wx,
                                         float& o0, float& o1)
{
    float acc0 = 0.0f, acc1 = 0.0f;
    #pragma unroll
    for (int r4 = 0; r4 < 4; r4++) {
        float rs0, rs1;
        rs0 = wx[0] * ldsI<OA>(a16[r4 * 4 + 0]);
        rs1 = wx[0] * ldsI<OB>(a16[r4 * 4 + 0]);
        rs0 = fmaf(wx[1], ldsI<OA>(a16[r4 * 4 + 1]), rs0);
        rs1 = fmaf(wx[1], ldsI<OB>(a16[r4 * 4 + 1]), rs1);
        rs0 = fmaf(wx[2], ldsI<OA>(a16[r4 * 4 + 2]), rs0);
        rs1 = fmaf(wx[2], ldsI<OB>(a16[r4 * 4 + 2]), rs1);
        rs0 = fmaf(wx[3], ldsI<OA>(a16[r4 * 4 + 3]), rs0);
        rs1 = fmaf(wx[3], ldsI<OB>(a16[r4 * 4 + 3]), rs1);
        acc0 = fmaf(wy[r4], rs0, acc0);
        acc1 = fmaf(wy[r4], rs1, acc1);
    }
    o0 = acc0; o1 = acc1;
}

__global__ __launch_bounds__(256, 4) void roialign_kernel(
    const float* __restrict__ feat,
    const float* __restrict__ rois,
    float* __restrict__ out)
{
    __shared__ float s_reg[PAIRS][4][RROWS * RSTRIDE];  // 44800 B

    const int k      = blockIdx.x;
    const int cbase  = blockIdx.y * CPB;
    const int tid    = threadIdx.x;
    const int wid    = tid >> 5;
    const int lane   = tid & 31;
    const int pair   = wid >> 1;
    const int lane64 = ((wid & 1) << 5) + lane;   // 0..63 within pair

    // --- RoI params (broadcast) ---
    const int   b  = (int)__ldg(rois + k * 5 + 0);
    const float x1 = __ldg(rois + k * 5 + 1);
    const float y1 = __ldg(rois + k * 5 + 2);
    const float x2 = __ldg(rois + k * 5 + 3);
    const float y2 = __ldg(rois + k * 5 + 4);

    const float sw = x1 * 0.25f - 0.5f;
    const float sh = y1 * 0.25f - 0.5f;
    const float bw = (x2 * 0.25f - 0.5f - sw) * (1.0f / 7.0f);
    const float bh = (y2 * 0.25f - 0.5f - sh) * (1.0f / 7.0f);

    // --- region bounds (samples monotone in ph/pw) ---
    float ya = fmaxf(sh + 0.25f * bh, 0.0f);
    int   y0 = (int)ya;          if (y0 >= FH - 1) y0 = FH - 1;
    float yb = fmaxf(sh + 6.75f * bh, 0.0f);
    int   yle = (int)yb;
    int   y1i = (yle >= FH - 1) ? (FH - 1) : (yle + 1);
    int   h = y1i - y0 + 1;      if (h > RROWS) h = RROWS;

    float xa = fmaxf(sw + 0.25f * bw, 0.0f);
    int   x0 = (int)xa;          if (x0 >= FW - 1) x0 = FW - 1;
    float xb = fmaxf(sw + 6.75f * bw, 0.0f);
    int   xle = (int)xb;
    int   x1i = (xle >= FW - 1) ? (FW - 1) : (xle + 1);

    const int x0a  = x0 & ~3;                 // 16B-aligned region start
    int       wext = x1i - x0a + 1;
    if (wext > RSTRIDE) wext = RSTRIDE;
    const int w4   = (wext + 3) >> 2;         // 16B chunks per row (<=7)

    const uint32_t s0 = (uint32_t)__cvta_generic_to_shared(&s_reg[pair][0][0]);

    const float* fb = feat + (size_t)b * (FC * FH * FW)
                           + (size_t)cbase * (FH * FW) + y0 * FW + x0a;
    float*       ob = out  + (size_t)k * (FC * OUTHW) + cbase * OUTHW;

    // staging lane mapping: flatten (row, 16B-chunk) over 64 lanes
    const int r_init = lane64 / w4;
    const int c_init = lane64 - r_init * w4;
    const int q64    = 64 / w4;
    const int rem64  = 64 - q64 * w4;

    // channel i of this pair = cbase + pair + PAIRS*i; buffer = i & 3
    auto stage = [&](int i) {
        const float* g = fb + (size_t)(pair + PAIRS * i) * (FH * FW);
        const uint32_t sb = s0 + (uint32_t)(i & 3) * BUFB;
        int r = r_init, c = c_init;
        #pragma unroll
        for (int it = 0; it < 3; it++) {
            if (r < h)
                cp16(sb + (r * (RSTRIDE * 4) + (c << 4)), g + r * FW + (c << 2));
            c += rem64;
            int carry = (c >= w4);
            r += q64 + carry;
            if (carry) c -= w4;
        }
        CP_COMMIT;
    };

    // prologue: fill all four buffers; tap math overlaps the flights
    stage(0);
    stage(1);
    stage(2);
    stage(3);

    // --- taps as absolute smem addresses into buffer 0 ---
    uint32_t a16[16];
    float    wy[4], wx[4];
    const int  p      = lane64;
    const bool active = (p < OUTHW);

    if (active) {
        const int ph = p / 7;
        const int pw = p - ph * 7;
        int yoff[4], xoff[4];

        #pragma unroll
        for (int i = 0; i < 2; i++) {
            float y = sh + (float)ph * bh + ((float)i + 0.5f) * (bh * 0.5f);
            y = fmaxf(y, 0.0f);
            int yl = (int)y;
            int yh = (yl >= FH - 1) ? (FH - 1) : (yl + 1);
            yl     = (yl >= FH - 1) ? (FH - 1) : yl;
            float ly = y - (float)yl;
            yoff[2 * i + 0] = (yl - y0) * RSTRIDE;  wy[2 * i + 0] = 0.25f * (1.0f - ly);
            yoff[2 * i + 1] = (yh - y0) * RSTRIDE;  wy[2 * i + 1] = 0.25f * ly;

            float x = sw + (float)pw * bw + ((float)i + 0.5f) * (bw * 0.5f);
            x = fmaxf(x, 0.0f);
            int xl = (int)x;
            int xh = (xl >= FW - 1) ? (FW - 1) : (xl + 1);
            xl     = (xl >= FW - 1) ? (FW - 1) : xl;
            float lx = x - (float)xl;
            xoff[2 * i + 0] = xl - x0a;  wx[2 * i + 0] = 1.0f - lx;
            xoff[2 * i + 1] = xh - x0a;  wx[2 * i + 1] = lx;
        }

        #pragma unroll
        for (int r4 = 0; r4 < 4; r4++)
            #pragma unroll
            for (int cx = 0; cx < 4; cx++)
                a16[r4 * 4 + cx] = s0 + (uint32_t)((yoff[r4] + xoff[cx]) << 2);
    }

    const int barid = pair + 1;   // named barriers 1..4 (0 reserved)
    float o0, o1;

    // j = 0: channels 0,1 (bufs 0,1); restage 4,5
    CP_WAIT(2);
    BAR64(barid);
    if (active) {
        compute2<0, 2800>(a16, wy, wx, o0, o1);
        ob[(pair + PAIRS * 0) * OUTHW + p] = o0;
        ob[(pair + PAIRS * 1) * OUTHW + p] = o1;
    }
    BAR64(barid);
    stage(4);
    stage(5);

    // j = 1: channels 2,3 (bufs 2,3); restage 6,7
    CP_WAIT(2);
    BAR64(barid);
    if (active) {
        compute2<5600, 8400>(a16, wy, wx, o0, o1);
        ob[(pair + PAIRS * 2) * OUTHW + p] = o0;
        ob[(pair + PAIRS * 3) * OUTHW + p] = o1;
    }
    BAR64(barid);
    stage(6);
    stage(7);

    // j = 2: channels 4,5 (bufs 0,1)
    CP_WAIT(2);
    BAR64(barid);
    if (active) {
        compute2<0, 2800>(a16, wy, wx, o0, o1);
        ob[(pair + PAIRS * 4) * OUTHW + p] = o0;
        ob[(pair + PAIRS * 5) * OUTHW + p] = o1;
    }

    // j = 3: channels 6,7 (bufs 2,3)
    CP_WAIT(0);
    BAR64(barid);
    if (active) {
        compute2<5600, 8400>(a16, wy, wx, o0, o1);
        ob[(pair + PAIRS * 6) * OUTHW + p] = o0;
        ob[(pair + PAIRS * 7) * OUTHW + p] = o1;
    }
}

extern "C" void kernel_launch(void* const* d_in, const int* in_sizes, int n_in,
                              void* d_out, int out_size)
{
    const float* feat = (const float*)d_in[0];
    const float* rois = (const float*)d_in[1];
    float*       out  = (float*)d_out;

    cudaFuncSetAttribute(roialign_kernel,
                         cudaFuncAttributePreferredSharedMemoryCarveout, 100);

    const int K = in_sizes[1] / 5;  // 512
    dim3 grid(K, CSPLIT);
    roialign_kernel<<<grid, 256>>>(feat, rois, out);
}

// round 16
// speedup vs baseline: 1.0040x; 1.0040x over previous
#include <cuda_runtime.h>
#include <cuda_bf16.h>
#include <cstdint>

// RoIAlign: feat [4,256,100,100] f32, rois [512,5] f32 -> out [512,256,7,7] f32
// SPATIAL_SCALE=0.25, SAMPLING_RATIO=2, ALIGNED=true, OUT 7x7.
//
// Two-kernel NHWC strategy:
//  1) transpose feat NCHW -> static NHWC scratch fT[b][y][x][c] (41MB
//     __device__ array; allowed scratch). Coalesced both sides via 32x32 tiles.
//  2) roialign: block = (roi, channel-half-128). Each warp owns a pixel
//     subset; per tap ONE coalesced LDG.128 serves 128 channels (lane=4ch).
//     No staging, no cp.async, no inner barriers. Results transposed through
//     SMEM so the final store is fully coalesced.

#define FH 100
#define FW 100
#define FC 256
#define OUTHW 49
#define SOSTRIDE 132   // s_out row stride (words): 16B-aligned, mod-4=0

__device__ __align__(16) float fT[4 * FH * FW * FC];  // NHWC scratch, 41MB

// ---------------- transpose: feat[b][c][y][x] -> fT[b][y][x][c] --------------
__global__ __launch_bounds__(256) void transpose_kernel(const float* __restrict__ feat)
{
    __shared__ float tile[32][33];
    const int by = blockIdx.x;          // b*100 + y
    const int xt = blockIdx.y;          // 0..3
    const int ct = blockIdx.z;          // 0..7
    const int tx = threadIdx.x & 31;
    const int ty = threadIdx.x >> 5;    // 0..7
    const int b  = by / FH;
    const int y  = by - b * FH;

    const int x = xt * 32 + tx;
    const float* src = feat + (size_t)b * FC * FH * FW + (size_t)y * FW;
    if (x < FW) {
        #pragma unroll
        for (int i = 0; i < 4; i++) {
            const int c = ct * 32 + ty + i * 8;
            tile[ty + i * 8][tx] = src[(size_t)c * (FH * FW) + x];
        }
    }
    __syncthreads();

    const int co = ct * 32 + tx;
    #pragma unroll
    for (int i = 0; i < 4; i++) {
        const int xi = xt * 32 + ty + i * 8;
        if (xi < FW)
            fT[((size_t)by * FW + xi) * FC + co] = tile[tx][ty + i * 8];
    }
}

// ---------------- roialign over NHWC ----------------------------------------
__global__ __launch_bounds__(256, 4) void roialign_kernel(
    const float* __restrict__ rois,
    float* __restrict__ out)
{
    __shared__ __align__(16) float s_out[OUTHW * SOSTRIDE];  // 25872 B

    const int k    = blockIdx.x;
    const int half = blockIdx.y;        // 0 or 1: channels half*128..+127
    const int tid  = threadIdx.x;
    const int wid  = tid >> 5;          // 0..7 : pixel group
    const int lane = tid & 31;          // 4 channels per lane

    // --- RoI params (broadcast) ---
    const int   b  = (int)__ldg(rois + k * 5 + 0);
    const float x1 = __ldg(rois + k * 5 + 1);
    const float y1 = __ldg(rois + k * 5 + 2);
    const float x2 = __ldg(rois + k * 5 + 3);
    const float y2 = __ldg(rois + k * 5 + 4);

    const float sw = x1 * 0.25f - 0.5f;
    const float sh = y1 * 0.25f - 0.5f;
    const float bw = (x2 * 0.25f - 0.5f - sw) * (1.0f / 7.0f);
    const float bh = (y2 * 0.25f - 0.5f - sh) * (1.0f / 7.0f);

    // base pointer for this (batch, channel-half, lane)
    const float* fbase = fT + (size_t)b * (FH * FW * FC) + half * 128 + lane * 4;

    // each warp: pixels p = wid, wid+8, ...
    for (int p = wid; p < OUTHW; p += 8) {
        const int ph = p / 7;
        const int pw = p - ph * 7;

        int   yr[4], xc[4];
        float wy[4], wx[4];

        #pragma unroll
        for (int i = 0; i < 2; i++) {
            float y = sh + (float)ph * bh + ((float)i + 0.5f) * (bh * 0.5f);
            y = fmaxf(y, 0.0f);
            int yl = (int)y;
            int yh = (yl >= FH - 1) ? (FH - 1) : (yl + 1);
            yl     = (yl >= FH - 1) ? (FH - 1) : yl;
            float ly = y - (float)yl;
            yr[2 * i + 0] = yl;  wy[2 * i + 0] = 0.25f * (1.0f - ly);
            yr[2 * i + 1] = yh;  wy[2 * i + 1] = 0.25f * ly;

            float x = sw + (float)pw * bw + ((float)i + 0.5f) * (bw * 0.5f);
            x = fmaxf(x, 0.0f);
            int xl = (int)x;
            int xh = (xl >= FW - 1) ? (FW - 1) : (xl + 1);
            xl     = (xl >= FW - 1) ? (FW - 1) : xl;
            float lx = x - (float)xl;
            xc[2 * i + 0] = xl;  wx[2 * i + 0] = 1.0f - lx;
            xc[2 * i + 1] = xh;  wx[2 * i + 1] = lx;
        }

        float4 acc = make_float4(0.f, 0.f, 0.f, 0.f);
        #pragma unroll
        for (int iy = 0; iy < 4; iy++) {
            const float* rp = fbase + (size_t)yr[iy] * (FW * FC);
            float4 rs = make_float4(0.f, 0.f, 0.f, 0.f);
            #pragma unroll
            for (int ix = 0; ix < 4; ix++) {
                const float4 v = __ldg((const float4*)(rp + (size_t)xc[ix] * FC));
                const float  w = wx[ix];
                rs.x = fmaf(w, v.x, rs.x);
                rs.y = fmaf(w, v.y, rs.y);
                rs.z = fmaf(w, v.z, rs.z);
                rs.w = fmaf(w, v.w, rs.w);
            }
            const float w = wy[iy];
            acc.x = fmaf(w, rs.x, acc.x);
            acc.y = fmaf(w, rs.y, acc.y);
            acc.z = fmaf(w, rs.z, acc.z);
            acc.w = fmaf(w, rs.w, acc.w);
        }

        // transpose through SMEM: s_out[p][c] (c = lane*4..+3), 16B aligned
        *(float4*)&s_out[p * SOSTRIDE + lane * 4] = acc;
    }
    __syncthreads();

    // coalesced store: idx = c*49 + p over 6272 elements
    float* ob = out + (size_t)k * (FC * OUTHW) + half * 128 * OUTHW;
    int c = tid / OUTHW;               // 0..5
    int p = tid - c * OUTHW;
    #pragma unroll 1
    for (int idx = tid; idx < 128 * OUTHW; idx += 256) {
        ob[idx] = s_out[p * SOSTRIDE + c];
        p += 11; c += 5;               // 256 = 5*49 + 11
        if (p >= OUTHW) { p -= OUTHW; c += 1; }
    }
}

extern "C" void kernel_launch(void* const* d_in, const int* in_sizes, int n_in,
                              void* d_out, int out_size)
{
    const float* feat = (const float*)d_in[0];
    const float* rois = (const float*)d_in[1];
    float*       out  = (float*)d_out;

    dim3 tg(4 * FH, 4, 8);             // (b*y, x-tiles, c-tiles)
    transpose_kernel<<<tg, 256>>>(feat);

    const int K = in_sizes[1] / 5;     // 512
    dim3 rg(K, 2);
    roialign_kernel<<<rg, 256>>>(rois, out);
}

// round 17
// speedup vs baseline: 1.0095x; 1.0054x over previous
#include <cuda_runtime.h>
#include <cuda_bf16.h>
#include <cstdint>

// RoIAlign: feat [4,256,100,100] f32, rois [512,5] f32 -> out [512,256,7,7] f32
// SPATIAL_SCALE=0.25, SAMPLING_RATIO=2, ALIGNED=true, OUT 7x7.
//
// Two-kernel NHWC strategy:
//  1) transpose feat NCHW -> static NHWC scratch fT[b][y][x][c], float4 on
//     BOTH global sides (x tiled by 4 on load, c by 4 on store).
//  2) roialign: block = (roi, channel-half-128); warp = pixel, lane = 4ch;
//     one coalesced LDG.128 per tap serves 128 channels. 32-bit offset math.
//     Output transposed through SMEM for coalesced stores.

#define FH 100
#define FW 100
#define FC 256
#define OUTHW 49
#define SOSTRIDE 132   // s_out row stride (words): 16B-aligned

__device__ __align__(16) float fT[4 * FH * FW * FC];  // NHWC scratch, 41MB

// ---------------- transpose: feat[b][c][y][x] -> fT[b][y][x][c] --------------
// tile: 32 x-values x 32 channels. Load float4 along x, store float4 along c.
__global__ __launch_bounds__(256) void transpose_kernel(const float* __restrict__ feat)
{
    __shared__ float tile[32][33];      // [x_local][c_local]
    const int by = blockIdx.x;          // b*100 + y
    const int xt = blockIdx.y;          // 0..3
    const int ct = blockIdx.z;          // 0..7
    const int t  = threadIdx.x;
    const int b  = by / FH;
    const int y  = by - b * FH;

    // load: thread -> (c_local = t/8, xq = t%8), float4 at x = xt*32 + xq*4
    {
        const int cl = t >> 3;
        const int xq = t & 7;
        const int x  = xt * 32 + xq * 4;
        if (x < FW) {
            const float4 v = *(const float4*)(feat
                + (size_t)b * (FC * FH * FW)
                + (size_t)(ct * 32 + cl) * (FH * FW)
                + y * FW + x);
            tile[xq * 4 + 0][cl] = v.x;
            tile[xq * 4 + 1][cl] = v.y;
            tile[xq * 4 + 2][cl] = v.z;
            tile[xq * 4 + 3][cl] = v.w;
        }
    }
    __syncthreads();

    // store: thread -> (x_local = t/8, cq = t%8), float4 at c = ct*32 + cq*4
    {
        const int xl = t >> 3;
        const int cq = t & 7;
        const int x  = xt * 32 + xl;
        if (x < FW) {
            float4 v;
            v.x = tile[xl][cq * 4 + 0];
            v.y = tile[xl][cq * 4 + 1];
            v.z = tile[xl][cq * 4 + 2];
            v.w = tile[xl][cq * 4 + 3];
            *(float4*)(fT + ((size_t)by * FW + x) * FC + ct * 32 + cq * 4) = v;
        }
    }
}

// ---------------- roialign over NHWC ----------------------------------------
__global__ __launch_bounds__(256, 4) void roialign_kernel(
    const float* __restrict__ rois,
    float* __restrict__ out)
{
    __shared__ __align__(16) float s_out[OUTHW * SOSTRIDE];  // 25872 B

    const int k    = blockIdx.x;
    const int half = blockIdx.y;        // 0 or 1: channels half*128..+127
    const int tid  = threadIdx.x;
    const int wid  = tid >> 5;          // 0..7 : pixel group
    const int lane = tid & 31;          // 4 channels per lane

    // --- RoI params (broadcast) ---
    const int   b  = (int)__ldg(rois + k * 5 + 0);
    const float x1 = __ldg(rois + k * 5 + 1);
    const float y1 = __ldg(rois + k * 5 + 2);
    const float x2 = __ldg(rois + k * 5 + 3);
    const float y2 = __ldg(rois + k * 5 + 4);

    const float sw = x1 * 0.25f - 0.5f;
    const float sh = y1 * 0.25f - 0.5f;
    const float bw = (x2 * 0.25f - 0.5f - sw) * (1.0f / 7.0f);
    const float bh = (y2 * 0.25f - 0.5f - sh) * (1.0f / 7.0f);

    // base pointer for this (batch, channel-half, lane); 32-bit offsets after
    const float* fbase = fT + (size_t)b * (FH * FW * FC) + half * 128 + lane * 4;

    // each warp: pixels p = wid, wid+8, ...
    for (int p = wid; p < OUTHW; p += 8) {
        const int ph = p / 7;
        const int pw = p - ph * 7;

        int   off_y[4], off_x[4];       // 32-bit element offsets
        float wy[4], wx[4];

        #pragma unroll
        for (int i = 0; i < 2; i++) {
            float y = sh + (float)ph * bh + ((float)i + 0.5f) * (bh * 0.5f);
            y = fmaxf(y, 0.0f);
            int yl = (int)y;
            int yh = (yl >= FH - 1) ? (FH - 1) : (yl + 1);
            yl     = (yl >= FH - 1) ? (FH - 1) : yl;
            float ly = y - (float)yl;
            off_y[2 * i + 0] = yl * (FW * FC);  wy[2 * i + 0] = 0.25f * (1.0f - ly);
            off_y[2 * i + 1] = yh * (FW * FC);  wy[2 * i + 1] = 0.25f * ly;

            float x = sw + (float)pw * bw + ((float)i + 0.5f) * (bw * 0.5f);
            x = fmaxf(x, 0.0f);
            int xl = (int)x;
            int xh = (xl >= FW - 1) ? (FW - 1) : (xl + 1);
            xl     = (xl >= FW - 1) ? (FW - 1) : xl;
            float lx = x - (float)xl;
            off_x[2 * i + 0] = xl * FC;  wx[2 * i + 0] = 1.0f - lx;
            off_x[2 * i + 1] = xh * FC;  wx[2 * i + 1] = lx;
        }

        float4 acc = make_float4(0.f, 0.f, 0.f, 0.f);
        #pragma unroll
        for (int iy = 0; iy < 4; iy++) {
            float4 rs = make_float4(0.f, 0.f, 0.f, 0.f);
            #pragma unroll
            for (int ix = 0; ix < 4; ix++) {
                const float4 v = __ldg((const float4*)(fbase + (off_y[iy] + off_x[ix])));
                const float  w = wx[ix];
                rs.x = fmaf(w, v.x, rs.x);
                rs.y = fmaf(w, v.y, rs.y);
                rs.z = fmaf(w, v.z, rs.z);
                rs.w = fmaf(w, v.w, rs.w);
            }
            const float w = wy[iy];
            acc.x = fmaf(w, rs.x, acc.x);
            acc.y = fmaf(w, rs.y, acc.y);
            acc.z = fmaf(w, rs.z, acc.z);
            acc.w = fmaf(w, rs.w, acc.w);
        }

        // transpose through SMEM: s_out[p][c] (c = lane*4..+3)
        *(float4*)&s_out[p * SOSTRIDE + lane * 4] = acc;
    }
    __syncthreads();

    // coalesced store: idx = c*49 + p over 6272 elements
    float* ob = out + (size_t)k * (FC * OUTHW) + half * 128 * OUTHW;
    int c = tid / OUTHW;               // 0..5
    int p = tid - c * OUTHW;
    #pragma unroll 1
    for (int idx = tid; idx < 128 * OUTHW; idx += 256) {
        ob[idx] = s_out[p * SOSTRIDE + c];
        p += 11; c += 5;               // 256 = 5*49 + 11
        if (p >= OUTHW) { p -= OUTHW; c += 1; }
    }
}

extern "C" void kernel_launch(void* const* d_in, const int* in_sizes, int n_in,
                              void* d_out, int out_size)
{
    const float* feat = (const float*)d_in[0];
    const float* rois = (const float*)d_in[1];
    float*       out  = (float*)d_out;

    dim3 tg(4 * FH, 4, 8);             // (b*y, x-tiles, c-tiles)
    transpose_kernel<<<tg, 256>>>(feat);

    const int K = in_sizes[1] / 5;     // 512
    dim3 rg(K, 2);
    roialign_kernel<<<rg, 256>>>(rois, out);
}